// round 14
// baseline (speedup 1.0000x reference)
#include <cuda_runtime.h>

#define Hc 512
#define Wc 512
#define Bc 8
#define HW (Hc * Wc)
#define HWF2 (HW / 2)   // stride in float2 units
#define ROWSTEP 8       // second row handled by same thread: y + 8

__device__ __forceinline__ float bilin(const float* __restrict__ dep, float py, float px) {
    const float fy = floorf(py);
    const float fx = floorf(px);
    const float ty = py - fy;
    const float tx = px - fx;
    const int y0 = (int)fy;
    const int x0 = (int)fx;

    float v00 = 0.f, v01 = 0.f, v10 = 0.f, v11 = 0.f;
    const int base = y0 * Wc + x0;
    const bool yi0 = (unsigned)y0       < (unsigned)Hc;
    const bool yi1 = (unsigned)(y0 + 1) < (unsigned)Hc;
    const bool xi0 = (unsigned)x0       < (unsigned)Wc;
    const bool xi1 = (unsigned)(x0 + 1) < (unsigned)Wc;
    if (yi0 && xi0) v00 = __ldg(dep + base);
    if (yi0 && xi1) v01 = __ldg(dep + base + 1);
    if (yi1 && xi0) v10 = __ldg(dep + base + Wc);
    if (yi1 && xi1) v11 = __ldg(dep + base + Wc + 1);

    const float top = v00 + (v01 - v00) * tx;
    const float bot = v10 + (v11 - v10) * tx;
    return top + (bot - top) * ty;
}

__global__ __launch_bounds__(256, 3)
void ppd_kernel(const float* __restrict__ depth,
                const float* __restrict__ weight,
                const float* __restrict__ offset,
                float* __restrict__ out)
{
    const int x  = blockIdx.x * 64 + threadIdx.x * 2;    // x-pair base (even)
    const int y0r = blockIdx.y * 16 + threadIdx.y;        // row A
    const int y1r = y0r + ROWSTEP;                        // row B
    const int b  = blockIdx.z;
    const int p0 = y0r * Wc + x;
    const int p1 = y1r * Wc + x;

    const float* __restrict__ dep = depth + (size_t)b * HW;
    const float2* __restrict__ wp0 = (const float2*)(weight + (size_t)b * 9  * HW + p0);
    const float2* __restrict__ op0 = (const float2*)(offset + (size_t)b * 18 * HW + p0);
    const float2* __restrict__ wp1 = (const float2*)(weight + (size_t)b * 9  * HW + p1);
    const float2* __restrict__ op1 = (const float2*)(offset + (size_t)b * 18 * HW + p1);

    const float ybase0 = (float)(y0r - 1);
    const float ybase1 = (float)(y1r - 1);
    const float xbase0 = (float)(x - 1);
    const float xbase1 = (float)(x);     // (x+1) - 1

    // out = sum_k s_k*w_k - (sum_k w_k)/9 * sum_k s_k + d   (per pixel)
    float2 swA = make_float2(0.f, 0.f), ssA = make_float2(0.f, 0.f), wsA = make_float2(0.f, 0.f);
    float2 swB = make_float2(0.f, 0.f), ssB = make_float2(0.f, 0.f), wsB = make_float2(0.f, 0.f);

#pragma unroll
    for (int k = 0; k < 9; k++) {
        const int ky = k / 3;
        const int kx = k % 3;

        const float2 wkA  = __ldg(wp0 + k * HWF2);
        const float2 dyA  = __ldg(op0 + (2 * k)     * HWF2);
        const float2 dxA  = __ldg(op0 + (2 * k + 1) * HWF2);
        const float2 wkB  = __ldg(wp1 + k * HWF2);
        const float2 dyB  = __ldg(op1 + (2 * k)     * HWF2);
        const float2 dxB  = __ldg(op1 + (2 * k + 1) * HWF2);

        const float pykA = ybase0 + (float)ky;
        const float pykB = ybase1 + (float)ky;
        const float xk0  = xbase0 + (float)kx;
        const float xk1  = xbase1 + (float)kx;

        const float sA0 = bilin(dep, dyA.x + pykA, dxA.x + xk0);
        const float sA1 = bilin(dep, dyA.y + pykA, dxA.y + xk1);
        const float sB0 = bilin(dep, dyB.x + pykB, dxB.x + xk0);
        const float sB1 = bilin(dep, dyB.y + pykB, dxB.y + xk1);

        swA.x = fmaf(sA0, wkA.x, swA.x);  swA.y = fmaf(sA1, wkA.y, swA.y);
        ssA.x += sA0;                     ssA.y += sA1;
        wsA.x += wkA.x;                   wsA.y += wkA.y;

        swB.x = fmaf(sB0, wkB.x, swB.x);  swB.y = fmaf(sB1, wkB.y, swB.y);
        ssB.x += sB0;                     ssB.y += sB1;
        wsB.x += wkB.x;                   wsB.y += wkB.y;
    }

    const float2 dA = __ldg((const float2*)(dep + p0));
    const float2 dB = __ldg((const float2*)(dep + p1));

    float2 rA, rB;
    rA.x = fmaf(-wsA.x * (1.0f / 9.0f), ssA.x, swA.x) + dA.x;
    rA.y = fmaf(-wsA.y * (1.0f / 9.0f), ssA.y, swA.y) + dA.y;
    rB.x = fmaf(-wsB.x * (1.0f / 9.0f), ssB.x, swB.x) + dB.x;
    rB.y = fmaf(-wsB.y * (1.0f / 9.0f), ssB.y, swB.y) + dB.y;

    *(float2*)(out + (size_t)b * HW + p0) = rA;
    *(float2*)(out + (size_t)b * HW + p1) = rB;
}

extern "C" void kernel_launch(void* const* d_in, const int* in_sizes, int n_in,
                              void* d_out, int out_size) {
    (void)in_sizes; (void)n_in; (void)out_size;
    const float* depth  = (const float*)d_in[0];
    const float* weight = (const float*)d_in[1];
    const float* offset = (const float*)d_in[2];
    float* out = (float*)d_out;

    dim3 block(32, 8, 1);                 // 256 threads -> 64x16 pixel tile (2 rows/thread)
    dim3 grid(Wc / 64, Hc / 16, Bc);
    ppd_kernel<<<grid, block>>>(depth, weight, offset, out);
}